// round 2
// baseline (speedup 1.0000x reference)
#include <cuda_runtime.h>
#include <cuda_bf16.h>

// ---------------- Problem constants ----------------
#define Bb     4
#define Ll     2048
#define Dm     1024
#define Ns     16
#define BL     (Bb * Ll)        // 8192 rows
#define LN_EPS 1e-5f

// ---------------- Scratch (device globals; no allocs allowed) ----------------
__device__ float g_xproj[BL * 2 * Dm];   // 64 MB: [row][0:1024]=x_ssm, [1024:2048]=gate
__device__ float g_xconv[BL * Dm];       // 32 MB
__device__ float g_bc[BL * 2 * Ns];      // 1 MB: [row][0:16]=B, [16:32]=C
__device__ float g_dt[BL * Dm];          // 32 MB (already softplus'd)
__device__ float g_y[BL * Dm];           // 32 MB (scan output * silu(gate))
__device__ float g_out[BL * Dm];         // 32 MB (after out proj, before LN)

// ---------------- Generic fp32 NT GEMM:  C[M,N] = A[M,K] . B[N,K]^T + bias ----------------
// BM=BN=128, BK=8, 256 threads, 8x8 per thread. M%128==0, K%8==0 assumed; N guarded.
#define BM 128
#define BN 128
#define BK 8
#define TM 8
#define TN 8

__device__ __forceinline__ float softplus_f(float v) {
    return (v > 20.f) ? v : log1pf(__expf(v));
}

__device__ __forceinline__ void gemm_body(const float* __restrict__ A,
                                          const float* __restrict__ B,
                                          const float* __restrict__ bias,
                                          float* __restrict__ C,
                                          int M, int N, int K, int act)
{
    __shared__ __align__(16) float As[BK][BM];
    __shared__ __align__(16) float Bs[BK][BN];

    const int tid = threadIdx.x;
    const int bm = blockIdx.y * BM;
    const int bn = blockIdx.x * BN;

    const int ldRow = tid >> 1;           // 0..127
    const int ldCol = (tid & 1) * 4;      // 0 or 4

    const int tx = tid & 15;              // 0..15 -> N dir
    const int ty = tid >> 4;              // 0..15 -> M dir

    const bool bValid = (bn + ldRow) < N;

    const float* Aptr = A + (size_t)(bm + ldRow) * K + ldCol;
    const float* Bptr = B + (size_t)(bn + ldRow) * K + ldCol;

    float acc[TM][TN];
    #pragma unroll
    for (int i = 0; i < TM; i++)
        #pragma unroll
        for (int j = 0; j < TN; j++) acc[i][j] = 0.f;

    for (int k0 = 0; k0 < K; k0 += BK) {
        float4 a4 = *(const float4*)(Aptr + k0);
        float4 b4 = bValid ? *(const float4*)(Bptr + k0) : make_float4(0.f, 0.f, 0.f, 0.f);

        As[ldCol + 0][ldRow] = a4.x;
        As[ldCol + 1][ldRow] = a4.y;
        As[ldCol + 2][ldRow] = a4.z;
        As[ldCol + 3][ldRow] = a4.w;
        Bs[ldCol + 0][ldRow] = b4.x;
        Bs[ldCol + 1][ldRow] = b4.y;
        Bs[ldCol + 2][ldRow] = b4.z;
        Bs[ldCol + 3][ldRow] = b4.w;
        __syncthreads();

        #pragma unroll
        for (int k = 0; k < BK; k++) {
            float4 a0 = *(const float4*)&As[k][ty * TM];
            float4 a1 = *(const float4*)&As[k][ty * TM + 4];
            float4 b0 = *(const float4*)&Bs[k][tx * TN];
            float4 b1 = *(const float4*)&Bs[k][tx * TN + 4];
            float ra[TM] = {a0.x, a0.y, a0.z, a0.w, a1.x, a1.y, a1.z, a1.w};
            float rb[TN] = {b0.x, b0.y, b0.z, b0.w, b1.x, b1.y, b1.z, b1.w};
            #pragma unroll
            for (int i = 0; i < TM; i++)
                #pragma unroll
                for (int j = 0; j < TN; j++)
                    acc[i][j] = fmaf(ra[i], rb[j], acc[i][j]);
        }
        __syncthreads();
    }

    #pragma unroll
    for (int i = 0; i < TM; i++) {
        int m = bm + ty * TM + i;
        float* crow = C + (size_t)m * N + bn;
        #pragma unroll
        for (int j = 0; j < TN; j++) {
            int n = tx * TN + j;
            if (bn + n < N) {
                float v = acc[i][j] + bias[bn + n];
                if (act == 1) v = softplus_f(v);
                crow[n] = v;
            }
        }
    }
}

__global__ void __launch_bounds__(256)
k_gemm_inproj(const float* __restrict__ x, const float* __restrict__ w,
              const float* __restrict__ b)
{ gemm_body(x, w, b, g_xproj, BL, 2 * Dm, Dm, 0); }

__global__ void __launch_bounds__(256)
k_gemm_bc(const float* __restrict__ w, const float* __restrict__ b)
{ gemm_body(g_xconv, w, b, g_bc, BL, 2 * Ns, Dm, 0); }

__global__ void __launch_bounds__(256)
k_gemm_dt(const float* __restrict__ w, const float* __restrict__ b)
{ gemm_body(g_xconv, w, b, g_dt, BL, Dm, Dm, 1); }   // fused softplus

__global__ void __launch_bounds__(256)
k_gemm_out(const float* __restrict__ w, const float* __restrict__ b)
{ gemm_body(g_y, w, b, g_out, BL, Dm, Dm, 0); }

// ---------------- Causal depthwise conv1d (k=4, left-pad 3) + SiLU ----------------
__global__ void __launch_bounds__(256)
k_conv_silu(const float* __restrict__ conv_w, const float* __restrict__ conv_b)
{
    int idx = blockIdx.x * blockDim.x + threadIdx.x;   // over BL*Dm
    if (idx >= BL * Dm) return;
    int d  = idx & (Dm - 1);
    int bl = idx >> 10;
    int l  = bl & (Ll - 1);
    int b  = bl >> 11;

    float w0 = conv_w[d * 4 + 0];
    float w1 = conv_w[d * 4 + 1];
    float w2 = conv_w[d * 4 + 2];
    float w3 = conv_w[d * 4 + 3];

    const float* xp = g_xproj + (size_t)(b * Ll + l) * 2 * Dm + d;
    float acc = conv_b[d];
    acc = fmaf(w3, xp[0], acc);
    if (l >= 1) acc = fmaf(w2, xp[-2 * Dm], acc);
    if (l >= 2) acc = fmaf(w1, xp[-4 * Dm], acc);
    if (l >= 3) acc = fmaf(w0, xp[-6 * Dm], acc);

    float s = acc / (1.f + __expf(-acc));   // silu
    g_xconv[idx] = s;
}

// ---------------- Selective scan ----------------
// One thread per (b, d, n). Block = 128 threads = 8 d-channels x 16 states.
// h = h*exp(dt*A) + (dt*x)*B ; y = sum_n h*C + x*D ; then * silu(gate).
__global__ void __launch_bounds__(128)
k_scan(const float* __restrict__ A_log, const float* __restrict__ Dvec)
{
    const int tid = threadIdx.x;
    const int n  = tid & 15;
    const int dg = tid >> 4;                  // 0..7
    const int b    = blockIdx.x >> 7;         // /128
    const int dblk = blockIdx.x & 127;
    const int d = dblk * 8 + dg;

    const float An = -__expf(A_log[d * Ns + n]);
    const float Dv = Dvec[d];
    float h = 0.f;

    const float* p_dt = g_dt    + (size_t)(b * Ll) * Dm + d;
    const float* p_xc = g_xconv + (size_t)(b * Ll) * Dm + d;
    const float* p_b  = g_bc    + (size_t)(b * Ll) * 2 * Ns + n;
    const float* p_c  = p_b + Ns;
    const float* p_g  = g_xproj + (size_t)(b * Ll) * 2 * Dm + Dm + d;
    float*       p_y  = g_y     + (size_t)(b * Ll) * Dm + d;

    for (int l = 0; l < Ll; l++) {
        float dt = p_dt[(size_t)l * Dm];
        float xv = p_xc[(size_t)l * Dm];
        float Bv = p_b[(size_t)l * 2 * Ns];
        float Cv = p_c[(size_t)l * 2 * Ns];

        h = fmaf(h, __expf(dt * An), (dt * xv) * Bv);
        float p = h * Cv;
        p += __shfl_xor_sync(0xffffffffu, p, 8);
        p += __shfl_xor_sync(0xffffffffu, p, 4);
        p += __shfl_xor_sync(0xffffffffu, p, 2);
        p += __shfl_xor_sync(0xffffffffu, p, 1);
        if (n == 0) {
            float g = p_g[(size_t)l * 2 * Dm];            // gate
            float yv = p + xv * Dv;
            p_y[(size_t)l * Dm] = yv * (g / (1.f + __expf(-g)));
        }
    }
}

// ---------------- Residual + LayerNorm ----------------
__global__ void __launch_bounds__(256)
k_ln(const float* __restrict__ x, const float* __restrict__ gam,
     const float* __restrict__ bet, float* __restrict__ out)
{
    const int row = blockIdx.x;
    const int tid = threadIdx.x;

    float v[4];
    float s = 0.f, ss = 0.f;
    #pragma unroll
    for (int i = 0; i < 4; i++) {
        int d = tid + i * 256;
        float z = g_out[(size_t)row * Dm + d] + x[(size_t)row * Dm + d];
        v[i] = z; s += z; ss = fmaf(z, z, ss);
    }
    __shared__ float red[2][8];
    #pragma unroll
    for (int o = 16; o; o >>= 1) {
        s  += __shfl_xor_sync(0xffffffffu, s, o);
        ss += __shfl_xor_sync(0xffffffffu, ss, o);
    }
    if ((tid & 31) == 0) { red[0][tid >> 5] = s; red[1][tid >> 5] = ss; }
    __syncthreads();
    s = 0.f; ss = 0.f;
    #pragma unroll
    for (int i = 0; i < 8; i++) { s += red[0][i]; ss += red[1][i]; }

    const float mu  = s * (1.f / Dm);
    const float var = ss * (1.f / Dm) - mu * mu;
    const float rstd = rsqrtf(var + LN_EPS);

    #pragma unroll
    for (int i = 0; i < 4; i++) {
        int d = tid + i * 256;
        out[(size_t)row * Dm + d] = (v[i] - mu) * rstd * gam[d] + bet[d];
    }
}

// ---------------- Launch ----------------
extern "C" void kernel_launch(void* const* d_in, const int* in_sizes, int n_in,
                              void* d_out, int out_size)
{
    const float* x    = (const float*)d_in[0];
    const float* ipw  = (const float*)d_in[1];
    const float* ipb  = (const float*)d_in[2];
    const float* cw   = (const float*)d_in[3];
    const float* cb   = (const float*)d_in[4];
    const float* bcw  = (const float*)d_in[5];
    const float* bcb  = (const float*)d_in[6];
    const float* dtw  = (const float*)d_in[7];
    const float* dtb  = (const float*)d_in[8];
    const float* alog = (const float*)d_in[9];
    const float* Dv   = (const float*)d_in[10];
    const float* ow   = (const float*)d_in[11];
    const float* ob   = (const float*)d_in[12];
    const float* lng  = (const float*)d_in[13];
    const float* lnb  = (const float*)d_in[14];
    float* out = (float*)d_out;

    // 1) in_proj: (8192,1024) @ (2048,1024)^T -> (8192,2048)
    k_gemm_inproj<<<dim3(2 * Dm / BN, BL / BM), 256>>>(x, ipw, ipb);

    // 2) causal depthwise conv + silu
    k_conv_silu<<<(BL * Dm) / 256, 256>>>(cw, cb);

    // 3) BC projection: N=32
    k_gemm_bc<<<dim3(1, BL / BM), 256>>>(bcw, bcb);

    // 4) dt projection with fused softplus: N=1024
    k_gemm_dt<<<dim3(Dm / BN, BL / BM), 256>>>(dtw, dtb);

    // 5) selective scan + gate
    k_scan<<<Bb * (Dm / 8), 128>>>(alog, Dv);

    // 6) out projection
    k_gemm_out<<<dim3(Dm / BN, BL / BM), 256>>>(ow, ob);

    // 7) residual + layernorm
    k_ln<<<BL, 256>>>(x, lng, lnb, out);
}

// round 3
// speedup vs baseline: 1.8283x; 1.8283x over previous
#include <cuda_runtime.h>
#include <cuda_bf16.h>
#include <cstdint>

// ---------------- Problem constants ----------------
#define Bb     4
#define Ll     2048
#define Dm     1024
#define Ns     16
#define BL     (Bb * Ll)        // 8192 rows
#define LN_EPS 1e-5f

// ---------------- Scratch (device globals; no allocs allowed) ----------------
__device__ float g_xproj[BL * 2 * Dm];   // [row][0:1024]=x_ssm, [1024:2048]=gate
__device__ float g_xconv[BL * Dm];
__device__ float g_bc[BL * 2 * Ns];      // [row][0:16]=B, [16:32]=C
__device__ float g_dt[BL * Dm];          // softplus'd
__device__ float g_y[BL * Dm];
__device__ float g_out[BL * Dm];

__device__ __forceinline__ float softplus_f(float v) {
    return (v > 20.f) ? v : log1pf(__expf(v));
}

// ================= tf32 tensor-core GEMM =================
// C[M,N] = A[M,K] . B[N,K]^T + bias, M%128==0, N%128==0, K%16==0.
// 256 threads = 8 warps (2x4), warp tile 64x32 of m16n8k8 mma.
#define GBM 128
#define GBN 128
#define GBK 16
#define LDS_PAD 4
#define LDA (GBK + LDS_PAD)     // 20 floats per row

__device__ __forceinline__ uint32_t smem_u32(const void* p) {
    return (uint32_t)__cvta_generic_to_shared(p);
}
__device__ __forceinline__ void cp16(uint32_t dst, const void* src) {
    asm volatile("cp.async.cg.shared.global [%0], [%1], 16;\n" :: "r"(dst), "l"(src));
}
__device__ __forceinline__ void cp_commit() { asm volatile("cp.async.commit_group;\n"); }
template<int W> __device__ __forceinline__ void cp_wait() {
    asm volatile("cp.async.wait_group %0;\n" :: "n"(W));
}

__device__ __forceinline__ void mma_tf32(float& c0, float& c1, float& c2, float& c3,
                                         uint32_t a0, uint32_t a1, uint32_t a2, uint32_t a3,
                                         uint32_t b0, uint32_t b1) {
    asm volatile(
        "mma.sync.aligned.m16n8k8.row.col.f32.tf32.tf32.f32 "
        "{%0,%1,%2,%3},{%4,%5,%6,%7},{%8,%9},{%0,%1,%2,%3};\n"
        : "+f"(c0), "+f"(c1), "+f"(c2), "+f"(c3)
        : "r"(a0), "r"(a1), "r"(a2), "r"(a3), "r"(b0), "r"(b1));
}

template<int ACT>
__device__ __forceinline__ void gemm_tf32_body(const float* __restrict__ A,
                                               const float* __restrict__ Bw,
                                               const float* __restrict__ bias,
                                               float* __restrict__ C,
                                               int N, int K)
{
    __shared__ float As[2][GBM][LDA];
    __shared__ float Bs[2][GBN][LDA];

    const int tid  = threadIdx.x;
    const int lane = tid & 31;
    const int wid  = tid >> 5;
    const int g    = lane >> 2;      // 0..7
    const int tig  = lane & 3;       // 0..3
    const int warpM = wid >> 2;      // 0..1 -> m offset *64
    const int warpN = wid & 3;       // 0..3 -> n offset *32
    const int bm = blockIdx.y * GBM;
    const int bn = blockIdx.x * GBN;

    float c[4][4][4];
    #pragma unroll
    for (int mt = 0; mt < 4; mt++)
        #pragma unroll
        for (int nt = 0; nt < 4; nt++)
            #pragma unroll
            for (int r = 0; r < 4; r++) c[mt][nt][r] = 0.f;

    // staging: 512 float4 per tile, 2 per thread: idx=2*tid+i -> row=idx>>2, ch=idx&3
    const int s_row0 = (2 * tid + 0) >> 2, s_ch0 = (2 * tid + 0) & 3;
    const int s_row1 = (2 * tid + 1) >> 2, s_ch1 = (2 * tid + 1) & 3;
    const float* Arow0 = A  + (size_t)(bm + s_row0) * K + s_ch0 * 4;
    const float* Arow1 = A  + (size_t)(bm + s_row1) * K + s_ch1 * 4;
    const float* Brow0 = Bw + (size_t)(bn + s_row0) * K + s_ch0 * 4;
    const float* Brow1 = Bw + (size_t)(bn + s_row1) * K + s_ch1 * 4;
    uint32_t dA0 = smem_u32(&As[0][s_row0][s_ch0 * 4]);
    uint32_t dA1 = smem_u32(&As[0][s_row1][s_ch1 * 4]);
    uint32_t dB0 = smem_u32(&Bs[0][s_row0][s_ch0 * 4]);
    uint32_t dB1 = smem_u32(&Bs[0][s_row1][s_ch1 * 4]);
    const uint32_t bufStride = (uint32_t)(GBM * LDA * 4);  // bytes between buf0/buf1 (As), (Bs)

    // prologue: stage k0=0 into buf 0
    cp16(dA0, Arow0); cp16(dA1, Arow1);
    cp16(dB0, Brow0); cp16(dB1, Brow1);
    cp_commit();

    const int NK = K / GBK;
    for (int it = 0; it < NK; it++) {
        const int cur = it & 1;
        if (it + 1 < NK) {
            const int nxt = cur ^ 1;
            const int k0 = (it + 1) * GBK;
            cp16(dA0 + nxt * bufStride, Arow0 + k0);
            cp16(dA1 + nxt * bufStride, Arow1 + k0);
            cp16(dB0 + nxt * bufStride, Brow0 + k0);
            cp16(dB1 + nxt * bufStride, Brow1 + k0);
            cp_commit();
            cp_wait<1>();
        } else {
            cp_wait<0>();
        }
        __syncthreads();

        #pragma unroll
        for (int ks = 0; ks < 2; ks++) {
            const int kk = ks * 8;
            uint32_t a[4][4], bf[4][2];
            #pragma unroll
            for (int mt = 0; mt < 4; mt++) {
                const int m0 = warpM * 64 + mt * 16;
                a[mt][0] = __float_as_uint(As[cur][m0 + g    ][kk + tig    ]);
                a[mt][1] = __float_as_uint(As[cur][m0 + g + 8][kk + tig    ]);
                a[mt][2] = __float_as_uint(As[cur][m0 + g    ][kk + tig + 4]);
                a[mt][3] = __float_as_uint(As[cur][m0 + g + 8][kk + tig + 4]);
            }
            #pragma unroll
            for (int nt = 0; nt < 4; nt++) {
                const int n0 = warpN * 32 + nt * 8;
                bf[nt][0] = __float_as_uint(Bs[cur][n0 + g][kk + tig    ]);
                bf[nt][1] = __float_as_uint(Bs[cur][n0 + g][kk + tig + 4]);
            }
            #pragma unroll
            for (int mt = 0; mt < 4; mt++)
                #pragma unroll
                for (int nt = 0; nt < 4; nt++)
                    mma_tf32(c[mt][nt][0], c[mt][nt][1], c[mt][nt][2], c[mt][nt][3],
                             a[mt][0], a[mt][1], a[mt][2], a[mt][3],
                             bf[nt][0], bf[nt][1]);
        }
        __syncthreads();
    }

    // epilogue: bias (+softplus), float2 stores for rows g and g+8
    #pragma unroll
    for (int mt = 0; mt < 4; mt++) {
        const int m = bm + warpM * 64 + mt * 16 + g;
        #pragma unroll
        for (int nt = 0; nt < 4; nt++) {
            const int n = bn + warpN * 32 + nt * 8 + tig * 2;
            const float b0v = bias[n], b1v = bias[n + 1];
            float v0 = c[mt][nt][0] + b0v;
            float v1 = c[mt][nt][1] + b1v;
            float v2 = c[mt][nt][2] + b0v;
            float v3 = c[mt][nt][3] + b1v;
            if (ACT == 1) { v0 = softplus_f(v0); v1 = softplus_f(v1); v2 = softplus_f(v2); v3 = softplus_f(v3); }
            *(float2*)&C[(size_t)m * N + n]       = make_float2(v0, v1);
            *(float2*)&C[(size_t)(m + 8) * N + n] = make_float2(v2, v3);
        }
    }
}

__global__ void __launch_bounds__(256)
k_gemm_inproj(const float* __restrict__ x, const float* __restrict__ w,
              const float* __restrict__ b)
{ gemm_tf32_body<0>(x, w, b, g_xproj, 2 * Dm, Dm); }

__global__ void __launch_bounds__(256)
k_gemm_dt(const float* __restrict__ w, const float* __restrict__ b)
{ gemm_tf32_body<1>(g_xconv, w, b, g_dt, Dm, Dm); }

__global__ void __launch_bounds__(256)
k_gemm_out(const float* __restrict__ w, const float* __restrict__ b)
{ gemm_tf32_body<0>(g_y, w, b, g_out, Dm, Dm); }

// ================= thin BC projection: (8192,1024) @ (32,1024)^T =================
// 256 blocks x 32 rows; 256 thr = 32 rows x 8 col-groups x 4 cols.
__global__ void __launch_bounds__(256)
k_bc(const float* __restrict__ w, const float* __restrict__ bias)
{
    const int row = blockIdx.x * 32 + (threadIdx.x >> 3);
    const int cg  = threadIdx.x & 7;             // cols cg*4 .. cg*4+3
    const float* arow = g_xconv + (size_t)row * Dm;
    const float* w0 = w + (size_t)(cg * 4 + 0) * Dm;
    const float* w1 = w + (size_t)(cg * 4 + 1) * Dm;
    const float* w2 = w + (size_t)(cg * 4 + 2) * Dm;
    const float* w3 = w + (size_t)(cg * 4 + 3) * Dm;

    float a0 = 0.f, a1 = 0.f, a2 = 0.f, a3 = 0.f;
    for (int k = 0; k < Dm; k += 4) {
        float4 a = *(const float4*)(arow + k);
        float4 x0 = *(const float4*)(w0 + k);
        float4 x1 = *(const float4*)(w1 + k);
        float4 x2 = *(const float4*)(w2 + k);
        float4 x3 = *(const float4*)(w3 + k);
        a0 = fmaf(a.x, x0.x, fmaf(a.y, x0.y, fmaf(a.z, x0.z, fmaf(a.w, x0.w, a0))));
        a1 = fmaf(a.x, x1.x, fmaf(a.y, x1.y, fmaf(a.z, x1.z, fmaf(a.w, x1.w, a1))));
        a2 = fmaf(a.x, x2.x, fmaf(a.y, x2.y, fmaf(a.z, x2.z, fmaf(a.w, x2.w, a2))));
        a3 = fmaf(a.x, x3.x, fmaf(a.y, x3.y, fmaf(a.z, x3.z, fmaf(a.w, x3.w, a3))));
    }
    float* o = g_bc + (size_t)row * (2 * Ns) + cg * 4;
    o[0] = a0 + bias[cg * 4 + 0];
    o[1] = a1 + bias[cg * 4 + 1];
    o[2] = a2 + bias[cg * 4 + 2];
    o[3] = a3 + bias[cg * 4 + 3];
}

// ================= Causal depthwise conv1d (k=4) + SiLU =================
__global__ void __launch_bounds__(256)
k_conv_silu(const float* __restrict__ conv_w, const float* __restrict__ conv_b)
{
    int idx = blockIdx.x * blockDim.x + threadIdx.x;   // over BL*Dm
    if (idx >= BL * Dm) return;
    int d  = idx & (Dm - 1);
    int bl = idx >> 10;
    int l  = bl & (Ll - 1);
    int b  = bl >> 11;

    float w0 = conv_w[d * 4 + 0];
    float w1 = conv_w[d * 4 + 1];
    float w2 = conv_w[d * 4 + 2];
    float w3 = conv_w[d * 4 + 3];

    const float* xp = g_xproj + (size_t)(b * Ll + l) * 2 * Dm + d;
    float acc = conv_b[d];
    acc = fmaf(w3, xp[0], acc);
    if (l >= 1) acc = fmaf(w2, xp[-2 * Dm], acc);
    if (l >= 2) acc = fmaf(w1, xp[-4 * Dm], acc);
    if (l >= 3) acc = fmaf(w0, xp[-6 * Dm], acc);

    float s = acc / (1.f + __expf(-acc));   // silu
    g_xconv[idx] = s;
}

// ================= Selective scan =================
// One thread per (b, d, n). Block = 128 threads = 8 d x 16 n.
__global__ void __launch_bounds__(128)
k_scan(const float* __restrict__ A_log, const float* __restrict__ Dvec)
{
    const int tid = threadIdx.x;
    const int n  = tid & 15;
    const int dg = tid >> 4;
    const int b    = blockIdx.x >> 7;
    const int dblk = blockIdx.x & 127;
    const int d = dblk * 8 + dg;

    const float An = -__expf(A_log[d * Ns + n]);
    const float Dv = Dvec[d];
    float h = 0.f;

    const float* p_dt = g_dt    + (size_t)(b * Ll) * Dm + d;
    const float* p_xc = g_xconv + (size_t)(b * Ll) * Dm + d;
    const float* p_b  = g_bc    + (size_t)(b * Ll) * 2 * Ns + n;
    const float* p_g  = g_xproj + (size_t)(b * Ll) * 2 * Dm + Dm + d;
    float*       p_y  = g_y     + (size_t)(b * Ll) * Dm + d;

    // register double-buffer: issue next step's loads before serial chain
    float dt_c = p_dt[0];
    float xv_c = p_xc[0];
    float Bv_c = p_b[0];
    float Cv_c = p_b[Ns];

    for (int l = 0; l < Ll; l++) {
        float dt_n, xv_n, Bv_n, Cv_n;
        if (l + 1 < Ll) {
            dt_n = p_dt[(size_t)(l + 1) * Dm];
            xv_n = p_xc[(size_t)(l + 1) * Dm];
            Bv_n = p_b[(size_t)(l + 1) * 2 * Ns];
            Cv_n = p_b[(size_t)(l + 1) * 2 * Ns + Ns];
        }

        h = fmaf(h, __expf(dt_c * An), (dt_c * xv_c) * Bv_c);
        float p = h * Cv_c;
        p += __shfl_xor_sync(0xffffffffu, p, 8);
        p += __shfl_xor_sync(0xffffffffu, p, 4);
        p += __shfl_xor_sync(0xffffffffu, p, 2);
        p += __shfl_xor_sync(0xffffffffu, p, 1);
        if (n == 0) {
            float gg = p_g[(size_t)l * 2 * Dm];           // gate
            float yv = p + xv_c * Dv;
            p_y[(size_t)l * Dm] = yv * (gg / (1.f + __expf(-gg)));
        }

        dt_c = dt_n; xv_c = xv_n; Bv_c = Bv_n; Cv_c = Cv_n;
    }
}

// ================= Residual + LayerNorm =================
__global__ void __launch_bounds__(256)
k_ln(const float* __restrict__ x, const float* __restrict__ gam,
     const float* __restrict__ bet, float* __restrict__ out)
{
    const int row = blockIdx.x;
    const int tid = threadIdx.x;

    float v[4];
    float s = 0.f, ss = 0.f;
    #pragma unroll
    for (int i = 0; i < 4; i++) {
        int d = tid + i * 256;
        float z = g_out[(size_t)row * Dm + d] + x[(size_t)row * Dm + d];
        v[i] = z; s += z; ss = fmaf(z, z, ss);
    }
    __shared__ float red[2][8];
    #pragma unroll
    for (int o = 16; o; o >>= 1) {
        s  += __shfl_xor_sync(0xffffffffu, s, o);
        ss += __shfl_xor_sync(0xffffffffu, ss, o);
    }
    if ((tid & 31) == 0) { red[0][tid >> 5] = s; red[1][tid >> 5] = ss; }
    __syncthreads();
    s = 0.f; ss = 0.f;
    #pragma unroll
    for (int i = 0; i < 8; i++) { s += red[0][i]; ss += red[1][i]; }

    const float mu  = s * (1.f / Dm);
    const float var = ss * (1.f / Dm) - mu * mu;
    const float rstd = rsqrtf(var + LN_EPS);

    #pragma unroll
    for (int i = 0; i < 4; i++) {
        int d = tid + i * 256;
        out[(size_t)row * Dm + d] = (v[i] - mu) * rstd * gam[d] + bet[d];
    }
}

// ================= Launch =================
extern "C" void kernel_launch(void* const* d_in, const int* in_sizes, int n_in,
                              void* d_out, int out_size)
{
    const float* x    = (const float*)d_in[0];
    const float* ipw  = (const float*)d_in[1];
    const float* ipb  = (const float*)d_in[2];
    const float* cw   = (const float*)d_in[3];
    const float* cb   = (const float*)d_in[4];
    const float* bcw  = (const float*)d_in[5];
    const float* bcb  = (const float*)d_in[6];
    const float* dtw  = (const float*)d_in[7];
    const float* dtb  = (const float*)d_in[8];
    const float* alog = (const float*)d_in[9];
    const float* Dv   = (const float*)d_in[10];
    const float* ow   = (const float*)d_in[11];
    const float* ob   = (const float*)d_in[12];
    const float* lng  = (const float*)d_in[13];
    const float* lnb  = (const float*)d_in[14];
    float* out = (float*)d_out;

    // 1) in_proj (tf32 tensor cores): (8192,1024)@(2048,1024)^T
    k_gemm_inproj<<<dim3(2 * Dm / GBN, BL / GBM), 256>>>(x, ipw, ipb);

    // 2) causal depthwise conv + silu
    k_conv_silu<<<(BL * Dm) / 256, 256>>>(cw, cb);

    // 3) BC projection (thin)
    k_bc<<<BL / 32, 256>>>(bcw, bcb);

    // 4) dt projection + fused softplus (tf32)
    k_gemm_dt<<<dim3(Dm / GBN, BL / GBM), 256>>>(dtw, dtb);

    // 5) selective scan + gate
    k_scan<<<Bb * (Dm / 8), 128>>>(alog, Dv);

    // 6) out projection (tf32)
    k_gemm_out<<<dim3(Dm / GBN, BL / GBM), 256>>>(ow, ob);

    // 7) residual + layernorm
    k_ln<<<BL, 256>>>(x, lng, lnb, out);
}

// round 5
// speedup vs baseline: 2.9758x; 1.6276x over previous
#include <cuda_runtime.h>
#include <cuda_bf16.h>
#include <cstdint>

// ---------------- Problem constants ----------------
#define Bb     4
#define Ll     2048
#define Dm     1024
#define Ns     16
#define BL     (Bb * Ll)        // 8192 rows
#define LN_EPS 1e-5f

// ---------------- Scratch (device globals; no allocs allowed) ----------------
__device__ float g_xproj[BL * 2 * Dm];   // [row][0:1024]=x_ssm, [1024:2048]=gate
__device__ float g_xconv[BL * Dm];
__device__ float g_bc[BL * 2 * Ns];      // [row][0:16]=B, [16:32]=C
__device__ float g_dt[BL * Dm];          // softplus'd
__device__ float g_y[BL * Dm];
__device__ float g_out[BL * Dm];

__device__ __forceinline__ float softplus_f(float v) {
    return (v > 20.f) ? v : log1pf(__expf(v));
}

__device__ __forceinline__ uint32_t smem_u32(const void* p) {
    return (uint32_t)__cvta_generic_to_shared(p);
}
__device__ __forceinline__ void cp16(uint32_t dst, const void* src) {
    asm volatile("cp.async.cg.shared.global [%0], [%1], 16;\n" :: "r"(dst), "l"(src));
}
__device__ __forceinline__ void cp_commit() { asm volatile("cp.async.commit_group;\n"); }
template<int W> __device__ __forceinline__ void cp_wait() {
    asm volatile("cp.async.wait_group %0;\n" :: "n"(W));
}

// ================= tf32 tensor-core GEMM =================
// C[M,N] = A[M,K] . B[N,K]^T + bias, M%128==0, N%128==0, K%16==0.
// 256 threads = 8 warps (2x4), warp tile 64x32 of m16n8k8 mma.
#define GBM 128
#define GBN 128
#define GBK 16
#define LDS_PAD 4
#define LDA (GBK + LDS_PAD)     // 20 floats per row

__device__ __forceinline__ void mma_tf32(float& c0, float& c1, float& c2, float& c3,
                                         uint32_t a0, uint32_t a1, uint32_t a2, uint32_t a3,
                                         uint32_t b0, uint32_t b1) {
    asm volatile(
        "mma.sync.aligned.m16n8k8.row.col.f32.tf32.tf32.f32 "
        "{%0,%1,%2,%3},{%4,%5,%6,%7},{%8,%9},{%0,%1,%2,%3};\n"
        : "+f"(c0), "+f"(c1), "+f"(c2), "+f"(c3)
        : "r"(a0), "r"(a1), "r"(a2), "r"(a3), "r"(b0), "r"(b1));
}

template<int ACT>
__device__ __forceinline__ void gemm_tf32_body(const float* __restrict__ A,
                                               const float* __restrict__ Bw,
                                               const float* __restrict__ bias,
                                               float* __restrict__ C,
                                               int N, int K)
{
    __shared__ float As[2][GBM][LDA];
    __shared__ float Bs[2][GBN][LDA];

    const int tid  = threadIdx.x;
    const int lane = tid & 31;
    const int wid  = tid >> 5;
    const int g    = lane >> 2;      // 0..7
    const int tig  = lane & 3;       // 0..3
    const int warpM = wid >> 2;      // 0..1 -> m offset *64
    const int warpN = wid & 3;       // 0..3 -> n offset *32
    const int bm = blockIdx.y * GBM;
    const int bn = blockIdx.x * GBN;

    float c[4][4][4];
    #pragma unroll
    for (int mt = 0; mt < 4; mt++)
        #pragma unroll
        for (int nt = 0; nt < 4; nt++)
            #pragma unroll
            for (int r = 0; r < 4; r++) c[mt][nt][r] = 0.f;

    // staging: 512 float4 per tile, 2 per thread: idx=2*tid+i -> row=idx>>2, ch=idx&3
    const int s_row0 = (2 * tid + 0) >> 2, s_ch0 = (2 * tid + 0) & 3;
    const int s_row1 = (2 * tid + 1) >> 2, s_ch1 = (2 * tid + 1) & 3;
    const float* Arow0 = A  + (size_t)(bm + s_row0) * K + s_ch0 * 4;
    const float* Arow1 = A  + (size_t)(bm + s_row1) * K + s_ch1 * 4;
    const float* Brow0 = Bw + (size_t)(bn + s_row0) * K + s_ch0 * 4;
    const float* Brow1 = Bw + (size_t)(bn + s_row1) * K + s_ch1 * 4;
    uint32_t dA0 = smem_u32(&As[0][s_row0][s_ch0 * 4]);
    uint32_t dA1 = smem_u32(&As[0][s_row1][s_ch1 * 4]);
    uint32_t dB0 = smem_u32(&Bs[0][s_row0][s_ch0 * 4]);
    uint32_t dB1 = smem_u32(&Bs[0][s_row1][s_ch1 * 4]);
    const uint32_t bufStride = (uint32_t)(GBM * LDA * 4);  // bytes between buf0/buf1

    // prologue: stage k0=0 into buf 0
    cp16(dA0, Arow0); cp16(dA1, Arow1);
    cp16(dB0, Brow0); cp16(dB1, Brow1);
    cp_commit();

    const int NK = K / GBK;
    for (int it = 0; it < NK; it++) {
        const int cur = it & 1;
        if (it + 1 < NK) {
            const int nxt = cur ^ 1;
            const int k0 = (it + 1) * GBK;
            cp16(dA0 + nxt * bufStride, Arow0 + k0);
            cp16(dA1 + nxt * bufStride, Arow1 + k0);
            cp16(dB0 + nxt * bufStride, Brow0 + k0);
            cp16(dB1 + nxt * bufStride, Brow1 + k0);
            cp_commit();
            cp_wait<1>();
        } else {
            cp_wait<0>();
        }
        __syncthreads();

        #pragma unroll
        for (int ks = 0; ks < 2; ks++) {
            const int kk = ks * 8;
            uint32_t a[4][4], bf[4][2];
            #pragma unroll
            for (int mt = 0; mt < 4; mt++) {
                const int m0 = warpM * 64 + mt * 16;
                a[mt][0] = __float_as_uint(As[cur][m0 + g    ][kk + tig    ]);
                a[mt][1] = __float_as_uint(As[cur][m0 + g + 8][kk + tig    ]);
                a[mt][2] = __float_as_uint(As[cur][m0 + g    ][kk + tig + 4]);
                a[mt][3] = __float_as_uint(As[cur][m0 + g + 8][kk + tig + 4]);
            }
            #pragma unroll
            for (int nt = 0; nt < 4; nt++) {
                const int n0 = warpN * 32 + nt * 8;
                bf[nt][0] = __float_as_uint(Bs[cur][n0 + g][kk + tig    ]);
                bf[nt][1] = __float_as_uint(Bs[cur][n0 + g][kk + tig + 4]);
            }
            #pragma unroll
            for (int mt = 0; mt < 4; mt++)
                #pragma unroll
                for (int nt = 0; nt < 4; nt++)
                    mma_tf32(c[mt][nt][0], c[mt][nt][1], c[mt][nt][2], c[mt][nt][3],
                             a[mt][0], a[mt][1], a[mt][2], a[mt][3],
                             bf[nt][0], bf[nt][1]);
        }
        __syncthreads();
    }

    // epilogue: bias (+softplus), float2 stores for rows g and g+8
    #pragma unroll
    for (int mt = 0; mt < 4; mt++) {
        const int m = bm + warpM * 64 + mt * 16 + g;
        #pragma unroll
        for (int nt = 0; nt < 4; nt++) {
            const int n = bn + warpN * 32 + nt * 8 + tig * 2;
            const float b0v = bias[n], b1v = bias[n + 1];
            float v0 = c[mt][nt][0] + b0v;
            float v1 = c[mt][nt][1] + b1v;
            float v2 = c[mt][nt][2] + b0v;
            float v3 = c[mt][nt][3] + b1v;
            if (ACT == 1) { v0 = softplus_f(v0); v1 = softplus_f(v1); v2 = softplus_f(v2); v3 = softplus_f(v3); }
            *(float2*)&C[(size_t)m * N + n]       = make_float2(v0, v1);
            *(float2*)&C[(size_t)(m + 8) * N + n] = make_float2(v2, v3);
        }
    }
}

__global__ void __launch_bounds__(256)
k_gemm_inproj(const float* __restrict__ x, const float* __restrict__ w,
              const float* __restrict__ b)
{ gemm_tf32_body<0>(x, w, b, g_xproj, 2 * Dm, Dm); }

__global__ void __launch_bounds__(256)
k_gemm_dt(const float* __restrict__ w, const float* __restrict__ b)
{ gemm_tf32_body<1>(g_xconv, w, b, g_dt, Dm, Dm); }

__global__ void __launch_bounds__(256)
k_gemm_out(const float* __restrict__ w, const float* __restrict__ b)
{ gemm_tf32_body<0>(g_y, w, b, g_out, Dm, Dm); }

// ================= thin BC projection: (8192,1024) @ (32,1024)^T =================
__global__ void __launch_bounds__(256)
k_bc(const float* __restrict__ w, const float* __restrict__ bias)
{
    const int row = blockIdx.x * 32 + (threadIdx.x >> 3);
    const int cg  = threadIdx.x & 7;             // cols cg*4 .. cg*4+3
    const float* arow = g_xconv + (size_t)row * Dm;
    const float* w0 = w + (size_t)(cg * 4 + 0) * Dm;
    const float* w1 = w + (size_t)(cg * 4 + 1) * Dm;
    const float* w2 = w + (size_t)(cg * 4 + 2) * Dm;
    const float* w3 = w + (size_t)(cg * 4 + 3) * Dm;

    float a0 = 0.f, a1 = 0.f, a2 = 0.f, a3 = 0.f;
    for (int k = 0; k < Dm; k += 4) {
        float4 a = *(const float4*)(arow + k);
        float4 x0 = *(const float4*)(w0 + k);
        float4 x1 = *(const float4*)(w1 + k);
        float4 x2 = *(const float4*)(w2 + k);
        float4 x3 = *(const float4*)(w3 + k);
        a0 = fmaf(a.x, x0.x, fmaf(a.y, x0.y, fmaf(a.z, x0.z, fmaf(a.w, x0.w, a0))));
        a1 = fmaf(a.x, x1.x, fmaf(a.y, x1.y, fmaf(a.z, x1.z, fmaf(a.w, x1.w, a1))));
        a2 = fmaf(a.x, x2.x, fmaf(a.y, x2.y, fmaf(a.z, x2.z, fmaf(a.w, x2.w, a2))));
        a3 = fmaf(a.x, x3.x, fmaf(a.y, x3.y, fmaf(a.z, x3.z, fmaf(a.w, x3.w, a3))));
    }
    float* o = g_bc + (size_t)row * (2 * Ns) + cg * 4;
    o[0] = a0 + bias[cg * 4 + 0];
    o[1] = a1 + bias[cg * 4 + 1];
    o[2] = a2 + bias[cg * 4 + 2];
    o[3] = a3 + bias[cg * 4 + 3];
}

// ================= Causal depthwise conv1d (k=4) + SiLU =================
__global__ void __launch_bounds__(256)
k_conv_silu(const float* __restrict__ conv_w, const float* __restrict__ conv_b)
{
    int idx = blockIdx.x * blockDim.x + threadIdx.x;   // over BL*Dm
    if (idx >= BL * Dm) return;
    int d  = idx & (Dm - 1);
    int bl = idx >> 10;
    int l  = bl & (Ll - 1);
    int b  = bl >> 11;

    float w0 = conv_w[d * 4 + 0];
    float w1 = conv_w[d * 4 + 1];
    float w2 = conv_w[d * 4 + 2];
    float w3 = conv_w[d * 4 + 3];

    const float* xp = g_xproj + (size_t)(b * Ll + l) * 2 * Dm + d;
    float acc = conv_b[d];
    acc = fmaf(w3, xp[0], acc);
    if (l >= 1) acc = fmaf(w2, xp[-2 * Dm], acc);
    if (l >= 2) acc = fmaf(w1, xp[-4 * Dm], acc);
    if (l >= 3) acc = fmaf(w0, xp[-6 * Dm], acc);

    float s = acc / (1.f + __expf(-acc));   // silu
    g_xconv[idx] = s;
}

// ================= Selective scan (smem-tiled, cp.async double-buffered) =================
// Block = 128 threads = 8 d-channels x 16 states. Grid = b(4) x 128 d-blocks.
// Tiles of SCAN_T timesteps staged into smem; serial recurrence reads smem only.
#define SCAN_T 64
#define SCAN_NT (Ll / SCAN_T)     // 32

__global__ void __launch_bounds__(128)
k_scan(const float* __restrict__ A_log, const float* __restrict__ Dvec)
{
    __shared__ __align__(16) float s_dt[2][SCAN_T][8];
    __shared__ __align__(16) float s_xc[2][SCAN_T][8];
    __shared__ __align__(16) float s_g [2][SCAN_T][8];
    __shared__ __align__(16) float s_bc[2][SCAN_T][32];

    const int tid  = threadIdx.x;
    const int n  = tid & 15;
    const int dg = tid >> 4;                  // 0..7
    const int b    = blockIdx.x >> 7;
    const int dblk = blockIdx.x & 127;
    const int d = dblk * 8 + dg;
    const int r0 = b * Ll;

    const float An = -__expf(A_log[d * Ns + n]);
    const float Dv = Dvec[d];

    // global row bases (32B-granular slices for this block's 8 d-channels)
    const float* src_dt = g_dt    + (size_t)r0 * Dm + dblk * 8;
    const float* src_xc = g_xconv + (size_t)r0 * Dm + dblk * 8;
    const float* src_g  = g_xproj + (size_t)r0 * 2 * Dm + Dm + dblk * 8;
    const float* src_bc = g_bc    + (size_t)r0 * 2 * Ns;
    float*       p_y    = g_y     + (size_t)r0 * Dm + d;

    // per-thread chunk assignment:
    //  dt/xc/g: 128 chunks of 16B per tile -> 1 each: l = tid>>1, hf = (tid&1)*4
    //  bc:      512 chunks of 16B per tile -> 4 each
    const int c_l  = tid >> 1;
    const int c_hf = (tid & 1) * 4;

    #define LOAD_TILE(t, buf)                                                              \
    {                                                                                      \
        const int base_l = (t) * SCAN_T;                                                   \
        cp16(smem_u32(&s_dt[buf][c_l][c_hf]), src_dt + (size_t)(base_l + c_l) * Dm + c_hf);\
        cp16(smem_u32(&s_xc[buf][c_l][c_hf]), src_xc + (size_t)(base_l + c_l) * Dm + c_hf);\
        cp16(smem_u32(&s_g [buf][c_l][c_hf]), src_g  + (size_t)(base_l + c_l) * 2 * Dm + c_hf);\
        _Pragma("unroll")                                                                  \
        for (int i = tid; i < SCAN_T * 8; i += 128) {                                      \
            const int bl = i >> 3, bhf = (i & 7) * 4;                                      \
            cp16(smem_u32(&s_bc[buf][bl][bhf]), src_bc + (size_t)(base_l + bl) * 32 + bhf);\
        }                                                                                  \
        cp_commit();                                                                       \
    }

    LOAD_TILE(0, 0);

    float h = 0.f;
    for (int t = 0; t < SCAN_NT; t++) {
        const int cur = t & 1;
        if (t + 1 < SCAN_NT) {
            LOAD_TILE(t + 1, cur ^ 1);
            cp_wait<1>();
        } else {
            cp_wait<0>();
        }
        __syncthreads();

        const int gbase = t * SCAN_T;
        #pragma unroll 4
        for (int l = 0; l < SCAN_T; l++) {
            float dt = s_dt[cur][l][dg];
            float xv = s_xc[cur][l][dg];
            float Bv = s_bc[cur][l][n];
            float Cv = s_bc[cur][l][16 + n];

            h = fmaf(h, __expf(dt * An), (dt * xv) * Bv);
            float p = h * Cv;
            p += __shfl_xor_sync(0xffffffffu, p, 8);
            p += __shfl_xor_sync(0xffffffffu, p, 4);
            p += __shfl_xor_sync(0xffffffffu, p, 2);
            p += __shfl_xor_sync(0xffffffffu, p, 1);
            if (n == 0) {
                float gg = s_g[cur][l][dg];
                float yv = p + xv * Dv;
                p_y[(size_t)(gbase + l) * Dm] = yv * (gg / (1.f + __expf(-gg)));
            }
        }
        __syncthreads();
    }
    #undef LOAD_TILE
}

// ================= Residual + LayerNorm =================
__global__ void __launch_bounds__(256)
k_ln(const float* __restrict__ x, const float* __restrict__ gam,
     const float* __restrict__ bet, float* __restrict__ out)
{
    const int row = blockIdx.x;
    const int tid = threadIdx.x;

    float v[4];
    float s = 0.f, ss = 0.f;
    #pragma unroll
    for (int i = 0; i < 4; i++) {
        int d = tid + i * 256;
        float z = g_out[(size_t)row * Dm + d] + x[(size_t)row * Dm + d];
        v[i] = z; s += z; ss = fmaf(z, z, ss);
    }
    __shared__ float red[2][8];
    #pragma unroll
    for (int o = 16; o; o >>= 1) {
        s  += __shfl_xor_sync(0xffffffffu, s, o);
        ss += __shfl_xor_sync(0xffffffffu, ss, o);
    }
    if ((tid & 31) == 0) { red[0][tid >> 5] = s; red[1][tid >> 5] = ss; }
    __syncthreads();
    s = 0.f; ss = 0.f;
    #pragma unroll
    for (int i = 0; i < 8; i++) { s += red[0][i]; ss += red[1][i]; }

    const float mu  = s * (1.f / Dm);
    const float var = ss * (1.f / Dm) - mu * mu;
    const float rstd = rsqrtf(var + LN_EPS);

    #pragma unroll
    for (int i = 0; i < 4; i++) {
        int d = tid + i * 256;
        out[(size_t)row * Dm + d] = (v[i] - mu) * rstd * gam[d] + bet[d];
    }
}

// ================= Launch =================
extern "C" void kernel_launch(void* const* d_in, const int* in_sizes, int n_in,
                              void* d_out, int out_size)
{
    const float* x    = (const float*)d_in[0];
    const float* ipw  = (const float*)d_in[1];
    const float* ipb  = (const float*)d_in[2];
    const float* cw   = (const float*)d_in[3];
    const float* cb   = (const float*)d_in[4];
    const float* bcw  = (const float*)d_in[5];
    const float* bcb  = (const float*)d_in[6];
    const float* dtw  = (const float*)d_in[7];
    const float* dtb  = (const float*)d_in[8];
    const float* alog = (const float*)d_in[9];
    const float* Dv   = (const float*)d_in[10];
    const float* ow   = (const float*)d_in[11];
    const float* ob   = (const float*)d_in[12];
    const float* lng  = (const float*)d_in[13];
    const float* lnb  = (const float*)d_in[14];
    float* out = (float*)d_out;

    // 1) in_proj (tf32 tensor cores): (8192,1024)@(2048,1024)^T
    k_gemm_inproj<<<dim3(2 * Dm / GBN, BL / GBM), 256>>>(x, ipw, ipb);

    // 2) causal depthwise conv + silu
    k_conv_silu<<<(BL * Dm) / 256, 256>>>(cw, cb);

    // 3) BC projection (thin)
    k_bc<<<BL / 32, 256>>>(bcw, bcb);

    // 4) dt projection + fused softplus (tf32)
    k_gemm_dt<<<dim3(Dm / GBN, BL / GBM), 256>>>(dtw, dtb);

    // 5) selective scan + gate (smem-tiled)
    k_scan<<<Bb * (Dm / 8), 128>>>(alog, Dv);

    // 6) out projection (tf32)
    k_gemm_out<<<dim3(Dm / GBN, BL / GBM), 256>>>(ow, ob);

    // 7) residual + layernorm
    k_ln<<<BL, 256>>>(x, lng, lnb, out);
}